// round 12
// baseline (speedup 1.0000x reference)
#include <cuda_runtime.h>
#include <cuda_fp16.h>

// Problem constants
#define NB   4
#define NT   16
#define BTB  64            // NB*NT
#define NN   2000
#define DD   64
#define EE   32000
#define NEDG (EE + NN)     // edges + self loops = 34000
#define NDP  (NN * DD)     // elements per (b,t) slice
#define TOT  (BTB * NDP)   // 8,192,000 elements per activation buffer
#define PBLK 592           // prep blocks: four per SM, guaranteed co-resident
#define NPB  4             // nodes per prep block for sort (592*4 >= 2000)
#define SORTBUF 1024
#define GBLK 740           // GCN persistent blocks: five per SM, exact capacity

// ---------------- device scratch (no allocations allowed) ----------------
__device__ __half g_h0[TOT];           // 16.4 MB ping
__device__ __half g_h1[TOT];           // 16.4 MB pong
__device__ uint2  g_Wfrag[3 * 4 * 8 * 32];  // W in mma B-fragment order
__device__ float  g_bias[3 * DD];      // biases copied contiguous (fp32)
__device__ int    g_row[NN + 1];
__device__ int2   g_edge[NEDG];        // (col<<6, half2(w,w) bits), row-sorted
__device__ int    g_degi[NN];          // zero-init; scan resets each launch
__device__ float  g_dinv[NN];
__device__ int    g_cursor[NN];
__device__ float  g_gx[BTB * 4 * DD];  // precomputed x-part of LSTM gates
__device__ unsigned g_cnt;             // barrier arrivals (returns to 0)
__device__ unsigned g_gen;             // barrier generation (monotonic)

// exact silu (tail / accuracy-sensitive paths)
__device__ __forceinline__ float fsilu(float x) {
    return x / (1.0f + __expf(-x));
}
__device__ __forceinline__ float fsig(float x) {
    return 1.0f / (1.0f + __expf(-x));
}
// fast silu for GCN epilogue: silu(x) = h + h*tanh(h), h = x/2 (1 MUFU)
__device__ __forceinline__ float fsilu_a(float x) {
    float h = 0.5f * x;
    float t;
    asm("tanh.approx.f32 %0, %1;" : "=f"(t) : "f"(h));
    return fmaf(h, t, h);
}
__device__ __forceinline__ __half2 asH2(unsigned u) { return *(__half2*)&u; }

// software grid barrier (all nblk blocks resident)
__device__ __forceinline__ void gridbar(unsigned nblk) {
    __syncthreads();
    if (threadIdx.x == 0) {
        __threadfence();
        unsigned g = *(volatile unsigned*)&g_gen;   // snapshot BEFORE arrive
        if (atomicAdd(&g_cnt, 1) == nblk - 1) {
            atomicExch(&g_cnt, 0);
            __threadfence();
            atomicAdd(&g_gen, 1);
        } else {
            while (*(volatile unsigned*)&g_gen == g) { __nanosleep(32); }
            __threadfence();
        }
    }
    __syncthreads();
}

// ---------------- fused preprocessing (single launch, 4 blocks/SM) -------
__global__ void __launch_bounds__(256, 4)
k_prep(const float* __restrict__ x, const void* __restrict__ edges,
       const float* __restrict__ W1, const float* __restrict__ W2,
       const float* __restrict__ W3,
       const float* __restrict__ b1, const float* __restrict__ b2,
       const float* __restrict__ b3) {
    __shared__ int s64;
    __shared__ int chunk[256];
    __shared__ int2 se[SORTBUF];

    int tid = threadIdx.x;
    int gid = blockIdx.x * 256 + tid;
    const int stride = PBLK * 256;

    // per-block dtype detect (warp 0): int64 LE => high words of ids are 0
    if (tid < 32) {
        const int* e32 = (const int*)edges;
        int any = 0;
        for (int j = tid; j < 128; j += 32) any |= e32[2 * j + 1];
        any = __reduce_or_sync(0xffffffffu, any);
        if (tid == 0) s64 = (any == 0) ? 1 : 0;
    }
    __syncthreads();
    int is64 = s64;

    // Phase 1a: convert x -> g_h0
    for (int i = gid; i < TOT / 4; i += stride) {
        float4 v = ((const float4*)x)[i];
        __half2 h0 = __floats2half2_rn(v.x, v.y);
        __half2 h1 = __floats2half2_rn(v.z, v.w);
        uint2 o;
        o.x = *(unsigned*)&h0;
        o.y = *(unsigned*)&h1;
        ((uint2*)g_h0)[i] = o;
    }
    // Phase 1b: pack W into mma B-fragment order; copy biases contiguous
    for (int i = gid; i < 3 * 1024; i += stride) {
        int l = i >> 10, rem = i & 1023;
        int kc = rem >> 8, nt = (rem >> 5) & 7, lane = rem & 31;
        const float* Ws = (l == 0) ? W1 : (l == 1) ? W2 : W3;
        int k0 = (kc << 4) + ((lane & 3) << 1);
        int nc = (nt << 3) + (lane >> 2);
        __half2 f0 = __floats2half2_rn(Ws[k0 * 64 + nc], Ws[(k0 + 1) * 64 + nc]);
        __half2 f1 = __floats2half2_rn(Ws[(k0 + 8) * 64 + nc], Ws[(k0 + 9) * 64 + nc]);
        uint2 o;
        o.x = *(unsigned*)&f0;
        o.y = *(unsigned*)&f1;
        g_Wfrag[i] = o;
    }
    if (gid < 3 * DD) {
        const float* bs = (gid < DD) ? b1 : (gid < 2 * DD) ? b2 : b3;
        g_bias[gid] = bs[gid & 63];
    }
    // Phase 1c: degree histogram over dst
    for (int e = gid; e < EE; e += stride) {
        int d = is64 ? (int)((const long long*)edges)[EE + e]
                     : ((const int*)edges)[EE + e];
        atomicAdd(&g_degi[d], 1);
    }
    gridbar(PBLK);

    // Phase 2: exclusive scan (+1 self loop), dinv, cursors, reset degi
    if (blockIdx.x == 0) {
        int base = tid * 8;
        int vals[8];
        int s = 0;
        #pragma unroll
        for (int q = 0; q < 8; q++) {
            int idx = base + q;
            int v = 0;
            if (idx < NN) {
                v = g_degi[idx] + 1;
                g_degi[idx] = 0;
            }
            vals[q] = v;
            s += v;
        }
        chunk[tid] = s;
        __syncthreads();
        for (int off = 1; off < 256; off <<= 1) {
            int v = (tid >= off) ? chunk[tid - off] : 0;
            __syncthreads();
            chunk[tid] += v;
            __syncthreads();
        }
        int run = chunk[tid] - s;
        #pragma unroll
        for (int q = 0; q < 8; q++) {
            int idx = base + q;
            if (idx <= NN) g_row[idx] = run;
            if (idx < NN) {
                g_cursor[idx] = run;
                g_dinv[idx] = rsqrtf((float)vals[q]);
            }
            run += vals[q];
        }
    }
    gridbar(PBLK);

    // Phase 3: fill CSR (edges + self loops), weight packed as half2
    for (int e = gid; e < NEDG; e += stride) {
        int s, d;
        if (e < EE) {
            if (is64) {
                s = (int)((const long long*)edges)[e];
                d = (int)((const long long*)edges)[EE + e];
            } else {
                s = ((const int*)edges)[e];
                d = ((const int*)edges)[EE + e];
            }
        } else {
            s = d = e - EE;   // self loop
        }
        int pos = atomicAdd(&g_cursor[d], 1);
        __half2 hw = __float2half2_rn(g_dinv[s] * g_dinv[d]);
        g_edge[pos] = make_int2(s << 6, *(int*)&hw);
    }
    gridbar(PBLK);

    // Phase 4: per-row sort by col (deterministic summation order)
    int n0 = blockIdx.x * NPB;
    if (n0 < NN) {
        int n1 = n0 + NPB;
        if (n1 > NN) n1 = NN;
        int b0 = g_row[n0], b1e = g_row[n1];
        int cnt = b1e - b0;
        if (cnt <= SORTBUF) {
            for (int i = tid; i < cnt; i += 256) se[i] = g_edge[b0 + i];
            __syncthreads();
            for (int n = n0 + tid; n < n1; n += 256) {
                int r0 = g_row[n] - b0, r1 = g_row[n + 1] - b0;
                for (int i = r0 + 1; i < r1; i++) {
                    int2 key = se[i];
                    int j = i - 1;
                    while (j >= r0 && se[j].x > key.x) { se[j + 1] = se[j]; j--; }
                    se[j + 1] = key;
                }
            }
            __syncthreads();
            for (int i = tid; i < cnt; i += 256) g_edge[b0 + i] = se[i];
        } else {   // fallback (never expected)
            for (int n = n0 + tid; n < n1; n += 256) {
                int r0 = g_row[n], r1 = g_row[n + 1];
                for (int i = r0 + 1; i < r1; i++) {
                    int2 key = g_edge[i];
                    int j = i - 1;
                    while (j >= r0 && g_edge[j].x > key.x) {
                        g_edge[j + 1] = g_edge[j];
                        j--;
                    }
                    g_edge[j + 1] = key;
                }
            }
        }
    }
}

// ---------------- persistent 3-layer GCN (single launch) -----------------
// 740 blocks (5/SM exact). Each layer: node-strided loop of the R11 aggemm
// body; gridbar between layers. SiLU via tanh.approx (1 MUFU).
__global__ void __launch_bounds__(256, 5)
k_gcn3() {
    __shared__ __align__(16) __half sagg[64][72];

    int tid = threadIdx.x;
    int bid = blockIdx.x;

    int grp   = tid >> 3;          // slice 0..31 (also owns slice grp+32)
    int lane8 = (tid & 7) << 3;
    int w     = tid >> 5;
    int lane  = tid & 31;
    int mrow0 = (w & 3) << 4;
    int ncol0 = (w >> 2) << 5;
    int gg    = lane >> 2;
    int tg    = lane & 3;

    #pragma unroll 1
    for (int layer = 0; layer < 3; layer++) {
        const __half* in  = (layer == 1) ? g_h1 : g_h0;
        __half*       out = (layer == 1) ? g_h0 : g_h1;
        const float* bias = g_bias + layer * DD;
        const uint2* wf = g_Wfrag + layer * 1024;

        #pragma unroll 1
        for (int n = bid; n < NN; n += GBLK) {
            __syncthreads();   // protect sagg reuse across loop iterations
            int r0 = g_row[n];
            int deg = g_row[n + 1] - r0;

            // ---- Stage A: gather + HFMA2 accumulate ----
            const __half* p0 = in + grp * NDP + lane8;
            const __half* p1 = in + (grp + 32) * NDP + lane8;
            const int2* ep = g_edge + r0;

            __half2 z = __float2half2_rn(0.0f);
            __half2 a0 = z, a1 = z, a2 = z, a3 = z;
            __half2 b0 = z, b1 = z, b2 = z, b3 = z;

            #pragma unroll 4
            for (int j = 0; j < deg; j++) {
                int2 e = __ldg(ep + j);
                __half2 hw = asH2((unsigned)e.y);
                uint4 v0 = *(const uint4*)(p0 + e.x);
                uint4 v1 = *(const uint4*)(p1 + e.x);
                a0 = __hfma2(hw, asH2(v0.x), a0);
                a1 = __hfma2(hw, asH2(v0.y), a1);
                a2 = __hfma2(hw, asH2(v0.z), a2);
                a3 = __hfma2(hw, asH2(v0.w), a3);
                b0 = __hfma2(hw, asH2(v1.x), b0);
                b1 = __hfma2(hw, asH2(v1.y), b1);
                b2 = __hfma2(hw, asH2(v1.z), b2);
                b3 = __hfma2(hw, asH2(v1.w), b3);
            }
            {
                uint4 s0, s1;
                s0.x = *(unsigned*)&a0; s0.y = *(unsigned*)&a1;
                s0.z = *(unsigned*)&a2; s0.w = *(unsigned*)&a3;
                s1.x = *(unsigned*)&b0; s1.y = *(unsigned*)&b1;
                s1.z = *(unsigned*)&b2; s1.w = *(unsigned*)&b3;
                *(uint4*)&sagg[grp     ][lane8] = s0;
                *(uint4*)&sagg[grp + 32][lane8] = s1;
            }
            __syncthreads();

            // ---- Stage B: tensor-core GEMM (64x64x64), 8 warps ----
            float c[4][4];
            #pragma unroll
            for (int i = 0; i < 4; i++)
                #pragma unroll
                for (int j = 0; j < 4; j++) c[i][j] = 0.0f;

            #pragma unroll
            for (int kc = 0; kc < 4; kc++) {
                unsigned ra0, ra1, ra2, ra3;
                unsigned aaddr = (unsigned)__cvta_generic_to_shared(
                    &sagg[mrow0 + (lane & 15)][(kc << 4) + ((lane >> 4) << 3)]);
                asm volatile("ldmatrix.sync.aligned.m8n8.x4.shared.b16 {%0,%1,%2,%3}, [%4];"
                             : "=r"(ra0), "=r"(ra1), "=r"(ra2), "=r"(ra3) : "r"(aaddr));
                #pragma unroll
                for (int nt = 0; nt < 4; nt++) {
                    uint2 rb = __ldg(&wf[((kc << 3) + (ncol0 >> 3) + nt) * 32 + lane]);
                    asm volatile(
                        "mma.sync.aligned.m16n8k16.row.col.f32.f16.f16.f32 "
                        "{%0,%1,%2,%3}, {%4,%5,%6,%7}, {%8,%9}, {%0,%1,%2,%3};"
                        : "+f"(c[nt][0]), "+f"(c[nt][1]), "+f"(c[nt][2]), "+f"(c[nt][3])
                        : "r"(ra0), "r"(ra1), "r"(ra2), "r"(ra3), "r"(rb.x), "r"(rb.y));
                }
            }
            __syncthreads();

            // epilogue: bias + fast SiLU, staged back into sagg as fp16
            #pragma unroll
            for (int nt = 0; nt < 4; nt++) {
                int col = ncol0 + (nt << 3) + (tg << 1);
                float2 bv = __ldg((const float2*)&bias[col]);
                __half2 h0 = __floats2half2_rn(fsilu_a(c[nt][0] + bv.x),
                                               fsilu_a(c[nt][1] + bv.y));
                __half2 h1 = __floats2half2_rn(fsilu_a(c[nt][2] + bv.x),
                                               fsilu_a(c[nt][3] + bv.y));
                *(__half2*)&sagg[mrow0 + gg][col]     = h0;
                *(__half2*)&sagg[mrow0 + gg + 8][col] = h1;
            }
            __syncthreads();

            // coalesced store-out: 2x uint4 per thread
            {
                int obase = n << 6;
                int idx0 = tid, idx1 = tid + 256;
                int row0 = idx0 >> 3, cc0 = (idx0 & 7) << 3;
                int row1 = idx1 >> 3, cc1 = (idx1 & 7) << 3;
                uint4 v0 = *(uint4*)&sagg[row0][cc0];
                uint4 v1 = *(uint4*)&sagg[row1][cc1];
                *(uint4*)(out + row0 * NDP + obase + cc0) = v0;
                *(uint4*)(out + row1 * NDP + obase + cc1) = v1;
            }
        }
        if (layer < 2) gridbar(GBLK);
    }
}

// ---------------- fused pool + gx + LSTM + head (single launch) ----------
__global__ void __launch_bounds__(512)
k_tail(const float* __restrict__ Wih, const float* __restrict__ bih,
       const float* __restrict__ bhh, const float* __restrict__ Whh,
       const float* __restrict__ Wp1, const float* __restrict__ bp1,
       const float* __restrict__ Wp2, const float* __restrict__ bp2,
       const float* __restrict__ Wp3, const float* __restrict__ bp3,
       float* __restrict__ out) {
    __shared__ float2 sp[16][32];
    __shared__ __align__(16) float spool[64];
    int t = threadIdx.x;
    int bt = blockIdx.x;

    // ---- pool phase ----
    {
        int d2 = t & 31;
        int part = t >> 5;   // 16 partials
        const __half2* bp = (const __half2*)(g_h1 + bt * NDP) + d2;
        float2 a = make_float2(0.f, 0.f);
        for (int n0 = part; n0 < NN; n0 += 16) {
            float2 v = __half22float2(bp[n0 * 32]);
            a.x += v.x;
            a.y += v.y;
        }
        sp[part][d2] = a;
        __syncthreads();
        if (part == 0) {
            float2 tt = sp[0][d2];
            #pragma unroll
            for (int i = 1; i < 16; i++) {
                float2 v = sp[i][d2];
                tt.x += v.x;
                tt.y += v.y;
            }
            spool[2 * d2]     = tt.x * (1.0f / NN);
            spool[2 * d2 + 1] = tt.y * (1.0f / NN);
        }
    }
    __syncthreads();

    // ---- gx phase: gx[bt][g] = pooled . Wih[g] + bih[g] + bhh[g] --------
    if (t < 256) {
        int g = t;
        float acc = __ldg(&bih[g]) + __ldg(&bhh[g]);
        const float4* wr = (const float4*)(Wih + (g << 6));
        #pragma unroll
        for (int k4 = 0; k4 < 16; k4++) {
            float4 w = __ldg(wr + k4);
            float4 xv = *(const float4*)&spool[k4 << 2];
            acc += xv.x * w.x + xv.y * w.y + xv.z * w.z + xv.w * w.w;
        }
        g_gx[bt * 256 + g] = acc;
    }
    __syncthreads();

    // ---- barrier: non-zero blocks arrive and exit; block 0 waits --------
    if (blockIdx.x != 0) {
        if (t == 0) {
            __threadfence();
            atomicAdd(&g_cnt, 1);
        }
        return;
    }
    if (t == 0) {
        while (*(volatile unsigned*)&g_cnt != BTB - 1) {}
        atomicExch(&g_cnt, 0);   // reset for next launch
        __threadfence();
    }
    __syncthreads();

    // ---- LSTM recurrence (512 threads: gate g = t>>1, k-half q = t&1) ---
    __shared__ __align__(16) float sh[NB][DD];
    __shared__ float sg[NB][4 * DD];
    __shared__ float sz1[NB][2 * DD], sz2[NB][DD];
    int g = t >> 1, q = t & 1;

    float wh[32];
    {
        const float4* wr = (const float4*)(Whh + (g << 6) + (q << 5));
        #pragma unroll
        for (int i = 0; i < 8; i++) {
            float4 w = __ldg(wr + i);
            wh[4 * i] = w.x; wh[4 * i + 1] = w.y;
            wh[4 * i + 2] = w.z; wh[4 * i + 3] = w.w;
        }
    }
    int bA = q << 1, bB = bA + 1;
    float gxA[NT], gxB[NT];
    #pragma unroll
    for (int tt = 0; tt < NT; tt++) {
        gxA[tt] = __ldg(&g_gx[(bA * NT + tt) * 256 + g]);
        gxB[tt] = __ldg(&g_gx[(bB * NT + tt) * 256 + g]);
    }

    float creg = 0.0f;
    if (t < 256) sh[t >> 6][t & 63] = 0.0f;
    __syncthreads();

    #pragma unroll 1
    for (int step = 0; step < NT; step++) {
        float s0 = 0.f, s1 = 0.f, s2 = 0.f, s3 = 0.f;
        #pragma unroll
        for (int i = 0; i < 8; i++) {
            int off = (q << 5) + (i << 2);
            float4 h0 = *(const float4*)&sh[0][off];
            float4 h1 = *(const float4*)&sh[1][off];
            float4 h2 = *(const float4*)&sh[2][off];
            float4 h3 = *(const float4*)&sh[3][off];
            float w0 = wh[4 * i], w1 = wh[4 * i + 1], w2 = wh[4 * i + 2], w3 = wh[4 * i + 3];
            s0 += h0.x * w0 + h0.y * w1 + h0.z * w2 + h0.w * w3;
            s1 += h1.x * w0 + h1.y * w1 + h1.z * w2 + h1.w * w3;
            s2 += h2.x * w0 + h2.y * w1 + h2.z * w2 + h2.w * w3;
            s3 += h3.x * w0 + h3.y * w1 + h3.z * w2 + h3.w * w3;
        }
        s0 += __shfl_xor_sync(0xffffffffu, s0, 1);
        s1 += __shfl_xor_sync(0xffffffffu, s1, 1);
        s2 += __shfl_xor_sync(0xffffffffu, s2, 1);
        s3 += __shfl_xor_sync(0xffffffffu, s3, 1);
        float selA = (q == 0) ? s0 : s2;
        float selB = (q == 0) ? s1 : s3;
        sg[bA][g] = gxA[step] + selA;
        sg[bB][g] = gxB[step] + selB;
        __syncthreads();
        if (t < 256) {
            int b = t >> 6, d = t & 63;
            float ig = fsig(sg[b][d]);
            float fg = fsig(sg[b][64 + d]);
            float gv = tanhf(sg[b][128 + d]);
            float og = fsig(sg[b][192 + d]);
            creg = fg * creg + ig * gv;
            sh[b][d] = og * tanhf(creg);
        }
        __syncthreads();
    }

    // head: 64 -> 128 (silu) -> 64 (silu) -> 8
    {
        int b = t >> 7, j = t & 127;
        float acc = __ldg(&bp1[j]);
        #pragma unroll
        for (int k = 0; k < 64; k++) acc += sh[b][k] * __ldg(&Wp1[k * 128 + j]);
        sz1[b][j] = fsilu(acc);
    }
    __syncthreads();
    if (t < 256) {
        int b = t >> 6, j2 = t & 63;
        float acc = __ldg(&bp2[j2]);
        #pragma unroll
        for (int j = 0; j < 128; j++) acc += sz1[b][j] * __ldg(&Wp2[j * 64 + j2]);
        sz2[b][j2] = fsilu(acc);
    }
    __syncthreads();
    if (t < 32) {
        int b = t >> 3, o = t & 7;
        float acc = __ldg(&bp3[o]);
        #pragma unroll
        for (int j2 = 0; j2 < 64; j2++) acc += sz2[b][j2] * __ldg(&Wp3[j2 * 8 + o]);
        out[b * 8 + o] = acc;
    }
}

// ---------------- launch --------------------------------------------------
extern "C" void kernel_launch(void* const* d_in, const int* in_sizes, int n_in,
                              void* d_out, int out_size) {
    const float* x   = (const float*)d_in[0];
    const void*  ei  = d_in[1];
    const float* W1  = (const float*)d_in[2];
    const float* b1  = (const float*)d_in[3];
    const float* W2  = (const float*)d_in[4];
    const float* b2  = (const float*)d_in[5];
    const float* W3  = (const float*)d_in[6];
    const float* b3  = (const float*)d_in[7];
    const float* Wih = (const float*)d_in[8];
    const float* Whh = (const float*)d_in[9];
    const float* bih = (const float*)d_in[10];
    const float* bhh = (const float*)d_in[11];
    const float* Wp1 = (const float*)d_in[12];
    const float* bp1 = (const float*)d_in[13];
    const float* Wp2 = (const float*)d_in[14];
    const float* bp2 = (const float*)d_in[15];
    const float* Wp3 = (const float*)d_in[16];
    const float* bp3 = (const float*)d_in[17];
    float* out = (float*)d_out;

    k_prep<<<PBLK, 256>>>(x, ei, W1, W2, W3, b1, b2, b3);
    k_gcn3<<<GBLK, 256>>>();
    k_tail<<<BTB, 512>>>(Wih, bih, bhh, Whh,
                         Wp1, bp1, Wp2, bp2, Wp3, bp3, out);
}

// round 14
// speedup vs baseline: 1.0110x; 1.0110x over previous
#include <cuda_runtime.h>
#include <cuda_fp16.h>

// Problem constants
#define NB   4
#define NT   16
#define BTB  64            // NB*NT
#define NN   2000
#define DD   64
#define EE   32000
#define NEDG (EE + NN)     // edges + self loops = 34000
#define NDP  (NN * DD)     // elements per (b,t) slice
#define TOT  (BTB * NDP)   // 8,192,000 elements per activation buffer
#define PBLK 592           // prep blocks: four per SM, guaranteed co-resident
#define NPB  4             // nodes per prep block for sort (592*4 >= 2000)
#define SORTBUF 1024
#define GBLK 740           // GCN persistent blocks: five per SM, exact capacity
#define CVT4 (TOT / 4)     // conversion work in float4 units
#define CVTH (CVT4 / 2)    // half of it

// ---------------- device scratch (no allocations allowed) ----------------
__device__ __half g_h0[TOT];           // 16.4 MB ping
__device__ __half g_h1[TOT];           // 16.4 MB pong
__device__ uint2  g_Wfrag[3 * 4 * 8 * 32];  // W in mma B-fragment order
__device__ float  g_bias[3 * DD];      // biases copied contiguous (fp32)
__device__ int    g_row[NN + 1];
__device__ int2   g_edge[NEDG];        // (col<<6, half2(w,w) bits), row-sorted
__device__ int    g_degi[NN];          // zero-init; scan resets each launch
__device__ float  g_dinv[NN];
__device__ int    g_cursor[NN];
__device__ float  g_gx[BTB * 4 * DD];  // precomputed x-part of LSTM gates
__device__ unsigned g_cnt;             // barrier arrivals (returns to 0)
__device__ unsigned g_gen;             // barrier generation (monotonic)

// exact silu (tail / accuracy-sensitive paths)
__device__ __forceinline__ float fsilu(float x) {
    return x / (1.0f + __expf(-x));
}
__device__ __forceinline__ float fsig(float x) {
    return 1.0f / (1.0f + __expf(-x));
}
// fast silu for GCN epilogue: silu(x) = h + h*tanh(h), h = x/2 (1 MUFU)
__device__ __forceinline__ float fsilu_a(float x) {
    float h = 0.5f * x;
    float t;
    asm("tanh.approx.f32 %0, %1;" : "=f"(t) : "f"(h));
    return fmaf(h, t, h);
}
__device__ __forceinline__ __half2 asH2(unsigned u) { return *(__half2*)&u; }

// software grid barrier (all nblk blocks resident)
__device__ __forceinline__ void gridbar(unsigned nblk) {
    __syncthreads();
    if (threadIdx.x == 0) {
        __threadfence();
        unsigned g = *(volatile unsigned*)&g_gen;   // snapshot BEFORE arrive
        if (atomicAdd(&g_cnt, 1) == nblk - 1) {
            atomicExch(&g_cnt, 0);
            __threadfence();
            atomicAdd(&g_gen, 1);
        } else {
            while (*(volatile unsigned*)&g_gen == g) { __nanosleep(32); }
            __threadfence();
        }
    }
    __syncthreads();
}

// convert a range of x (float4 units) to fp16 with 4x-unrolled MLP
__device__ __forceinline__ void cvt_range(const float* __restrict__ x,
                                          int start, int end,
                                          int idx, int stride) {
    #pragma unroll 4
    for (int i = start + idx; i < end; i += stride) {
        float4 v = ((const float4*)x)[i];
        __half2 h0 = __floats2half2_rn(v.x, v.y);
        __half2 h1 = __floats2half2_rn(v.z, v.w);
        uint2 o;
        o.x = *(unsigned*)&h0;
        o.y = *(unsigned*)&h1;
        ((uint2*)g_h0)[i] = o;
    }
}

// ---------------- fused preprocessing (overlapped phases) ----------------
// P1: histogram + Wpack + bias. P2: block0 scans WHILE others convert x(A).
// P3: fill CSR. P4: sort (500 blocks) + convert x(B) (all blocks, no bar).
__global__ void __launch_bounds__(256, 4)
k_prep(const float* __restrict__ x, const void* __restrict__ edges,
       const float* __restrict__ W1, const float* __restrict__ W2,
       const float* __restrict__ W3,
       const float* __restrict__ b1, const float* __restrict__ b2,
       const float* __restrict__ b3) {
    __shared__ int s64;
    __shared__ int chunk[256];
    __shared__ int2 se[SORTBUF];

    int tid = threadIdx.x;
    int bid = blockIdx.x;
    int gid = bid * 256 + tid;
    const int stride = PBLK * 256;

    // per-block dtype detect (warp 0): int64 LE => high words of ids are 0
    if (tid < 32) {
        const int* e32 = (const int*)edges;
        int any = 0;
        for (int j = tid; j < 128; j += 32) any |= e32[2 * j + 1];
        any = __reduce_or_sync(0xffffffffu, any);
        if (tid == 0) s64 = (any == 0) ? 1 : 0;
    }
    __syncthreads();
    int is64 = s64;

    // ---- Phase 1: W pack + bias + degree histogram (NO x conversion) ----
    for (int i = gid; i < 3 * 1024; i += stride) {
        int l = i >> 10, rem = i & 1023;
        int kc = rem >> 8, nt = (rem >> 5) & 7, lane = rem & 31;
        const float* Ws = (l == 0) ? W1 : (l == 1) ? W2 : W3;
        int k0 = (kc << 4) + ((lane & 3) << 1);
        int nc = (nt << 3) + (lane >> 2);
        __half2 f0 = __floats2half2_rn(Ws[k0 * 64 + nc], Ws[(k0 + 1) * 64 + nc]);
        __half2 f1 = __floats2half2_rn(Ws[(k0 + 8) * 64 + nc], Ws[(k0 + 9) * 64 + nc]);
        uint2 o;
        o.x = *(unsigned*)&f0;
        o.y = *(unsigned*)&f1;
        g_Wfrag[i] = o;
    }
    if (gid < 3 * DD) {
        const float* bs = (gid < DD) ? b1 : (gid < 2 * DD) ? b2 : b3;
        g_bias[gid] = bs[gid & 63];
    }
    for (int e = gid; e < EE; e += stride) {
        int d = is64 ? (int)((const long long*)edges)[EE + e]
                     : ((const int*)edges)[EE + e];
        atomicAdd(&g_degi[d], 1);
    }
    gridbar(PBLK);

    // ---- Phase 2: block 0 scans; blocks 1..591 convert first half of x --
    if (bid == 0) {
        int base = tid * 8;
        int vals[8];
        int s = 0;
        #pragma unroll
        for (int q = 0; q < 8; q++) {
            int idx = base + q;
            int v = 0;
            if (idx < NN) {
                v = g_degi[idx] + 1;
                g_degi[idx] = 0;
            }
            vals[q] = v;
            s += v;
        }
        chunk[tid] = s;
        __syncthreads();
        for (int off = 1; off < 256; off <<= 1) {
            int v = (tid >= off) ? chunk[tid - off] : 0;
            __syncthreads();
            chunk[tid] += v;
            __syncthreads();
        }
        int run = chunk[tid] - s;
        #pragma unroll
        for (int q = 0; q < 8; q++) {
            int idx = base + q;
            if (idx <= NN) g_row[idx] = run;
            if (idx < NN) {
                g_cursor[idx] = run;
                g_dinv[idx] = rsqrtf((float)vals[q]);
            }
            run += vals[q];
        }
    } else {
        cvt_range(x, 0, CVTH, (bid - 1) * 256 + tid, (PBLK - 1) * 256);
    }
    gridbar(PBLK);

    // ---- Phase 3: fill CSR (edges + self loops) -------------------------
    for (int e = gid; e < NEDG; e += stride) {
        int s, d;
        if (e < EE) {
            if (is64) {
                s = (int)((const long long*)edges)[e];
                d = (int)((const long long*)edges)[EE + e];
            } else {
                s = ((const int*)edges)[e];
                d = ((const int*)edges)[EE + e];
            }
        } else {
            s = d = e - EE;   // self loop
        }
        int pos = atomicAdd(&g_cursor[d], 1);
        __half2 hw = __float2half2_rn(g_dinv[s] * g_dinv[d]);
        g_edge[pos] = make_int2(s << 6, *(int*)&hw);
    }
    gridbar(PBLK);

    // ---- Phase 4: sort (blocks 0..499) + convert second half (all) ------
    {
        int n0 = bid * NPB;
        if (n0 < NN) {
            int n1 = n0 + NPB;
            if (n1 > NN) n1 = NN;
            int b0 = g_row[n0], b1e = g_row[n1];
            int cnt = b1e - b0;
            if (cnt <= SORTBUF) {
                for (int i = tid; i < cnt; i += 256) se[i] = g_edge[b0 + i];
                __syncthreads();
                for (int n = n0 + tid; n < n1; n += 256) {
                    int r0 = g_row[n] - b0, r1 = g_row[n + 1] - b0;
                    for (int i = r0 + 1; i < r1; i++) {
                        int2 key = se[i];
                        int j = i - 1;
                        while (j >= r0 && se[j].x > key.x) { se[j + 1] = se[j]; j--; }
                        se[j + 1] = key;
                    }
                }
                __syncthreads();
                for (int i = tid; i < cnt; i += 256) g_edge[b0 + i] = se[i];
            } else {   // fallback (never expected)
                for (int n = n0 + tid; n < n1; n += 256) {
                    int r0 = g_row[n], r1 = g_row[n + 1];
                    for (int i = r0 + 1; i < r1; i++) {
                        int2 key = g_edge[i];
                        int j = i - 1;
                        while (j >= r0 && g_edge[j].x > key.x) {
                            g_edge[j + 1] = g_edge[j];
                            j--;
                        }
                        g_edge[j + 1] = key;
                    }
                }
            }
        }
    }
    // second half of x conversion; ends when done (kernel-end is the sync)
    cvt_range(x, CVTH, CVT4, gid, stride);
}

// ---------------- persistent 3-layer GCN (single launch) -----------------
__global__ void __launch_bounds__(256, 5)
k_gcn3() {
    __shared__ __align__(16) __half sagg[64][72];

    int tid = threadIdx.x;
    int bid = blockIdx.x;

    int grp   = tid >> 3;          // slice 0..31 (also owns slice grp+32)
    int lane8 = (tid & 7) << 3;
    int w     = tid >> 5;
    int lane  = tid & 31;
    int mrow0 = (w & 3) << 4;
    int ncol0 = (w >> 2) << 5;
    int gg    = lane >> 2;
    int tg    = lane & 3;

    #pragma unroll 1
    for (int layer = 0; layer < 3; layer++) {
        const __half* in  = (layer == 1) ? g_h1 : g_h0;
        __half*       out = (layer == 1) ? g_h0 : g_h1;
        const float* bias = g_bias + layer * DD;
        const uint2* wf = g_Wfrag + layer * 1024;

        #pragma unroll 1
        for (int n = bid; n < NN; n += GBLK) {
            __syncthreads();   // protect sagg reuse across loop iterations
            int r0 = g_row[n];
            int deg = g_row[n + 1] - r0;

            // ---- Stage A: gather + HFMA2 accumulate ----
            const __half* p0 = in + grp * NDP + lane8;
            const __half* p1 = in + (grp + 32) * NDP + lane8;
            const int2* ep = g_edge + r0;

            __half2 z = __float2half2_rn(0.0f);
            __half2 a0 = z, a1 = z, a2 = z, a3 = z;
            __half2 b0 = z, b1 = z, b2 = z, b3 = z;

            #pragma unroll 4
            for (int j = 0; j < deg; j++) {
                int2 e = __ldg(ep + j);
                __half2 hw = asH2((unsigned)e.y);
                uint4 v0 = *(const uint4*)(p0 + e.x);
                uint4 v1 = *(const uint4*)(p1 + e.x);
                a0 = __hfma2(hw, asH2(v0.x), a0);
                a1 = __hfma2(hw, asH2(v0.y), a1);
                a2 = __hfma2(hw, asH2(v0.z), a2);
                a3 = __hfma2(hw, asH2(v0.w), a3);
                b0 = __hfma2(hw, asH2(v1.x), b0);
                b1 = __hfma2(hw, asH2(v1.y), b1);
                b2 = __hfma2(hw, asH2(v1.z), b2);
                b3 = __hfma2(hw, asH2(v1.w), b3);
            }
            {
                uint4 s0, s1;
                s0.x = *(unsigned*)&a0; s0.y = *(unsigned*)&a1;
                s0.z = *(unsigned*)&a2; s0.w = *(unsigned*)&a3;
                s1.x = *(unsigned*)&b0; s1.y = *(unsigned*)&b1;
                s1.z = *(unsigned*)&b2; s1.w = *(unsigned*)&b3;
                *(uint4*)&sagg[grp     ][lane8] = s0;
                *(uint4*)&sagg[grp + 32][lane8] = s1;
            }
            __syncthreads();

            // ---- Stage B: tensor-core GEMM (64x64x64), 8 warps ----
            float c[4][4];
            #pragma unroll
            for (int i = 0; i < 4; i++)
                #pragma unroll
                for (int j = 0; j < 4; j++) c[i][j] = 0.0f;

            #pragma unroll
            for (int kc = 0; kc < 4; kc++) {
                unsigned ra0, ra1, ra2, ra3;
                unsigned aaddr = (unsigned)__cvta_generic_to_shared(
                    &sagg[mrow0 + (lane & 15)][(kc << 4) + ((lane >> 4) << 3)]);
                asm volatile("ldmatrix.sync.aligned.m8n8.x4.shared.b16 {%0,%1,%2,%3}, [%4];"
                             : "=r"(ra0), "=r"(ra1), "=r"(ra2), "=r"(ra3) : "r"(aaddr));
                #pragma unroll
                for (int nt = 0; nt < 4; nt++) {
                    uint2 rb = __ldg(&wf[((kc << 3) + (ncol0 >> 3) + nt) * 32 + lane]);
                    asm volatile(
                        "mma.sync.aligned.m16n8k16.row.col.f32.f16.f16.f32 "
                        "{%0,%1,%2,%3}, {%4,%5,%6,%7}, {%8,%9}, {%0,%1,%2,%3};"
                        : "+f"(c[nt][0]), "+f"(c[nt][1]), "+f"(c[nt][2]), "+f"(c[nt][3])
                        : "r"(ra0), "r"(ra1), "r"(ra2), "r"(ra3), "r"(rb.x), "r"(rb.y));
                }
            }
            __syncthreads();

            // epilogue: bias + fast SiLU, staged back into sagg as fp16
            #pragma unroll
            for (int nt = 0; nt < 4; nt++) {
                int col = ncol0 + (nt << 3) + (tg << 1);
                float2 bv = __ldg((const float2*)&bias[col]);
                __half2 h0 = __floats2half2_rn(fsilu_a(c[nt][0] + bv.x),
                                               fsilu_a(c[nt][1] + bv.y));
                __half2 h1 = __floats2half2_rn(fsilu_a(c[nt][2] + bv.x),
                                               fsilu_a(c[nt][3] + bv.y));
                *(__half2*)&sagg[mrow0 + gg][col]     = h0;
                *(__half2*)&sagg[mrow0 + gg + 8][col] = h1;
            }
            __syncthreads();

            // coalesced store-out: 2x uint4 per thread
            {
                int obase = n << 6;
                int idx0 = tid, idx1 = tid + 256;
                int row0 = idx0 >> 3, cc0 = (idx0 & 7) << 3;
                int row1 = idx1 >> 3, cc1 = (idx1 & 7) << 3;
                uint4 v0 = *(uint4*)&sagg[row0][cc0];
                uint4 v1 = *(uint4*)&sagg[row1][cc1];
                *(uint4*)(out + row0 * NDP + obase + cc0) = v0;
                *(uint4*)(out + row1 * NDP + obase + cc1) = v1;
            }
        }
        if (layer < 2) gridbar(GBLK);
    }
}

// ---------------- fused pool + gx + LSTM + head (single launch) ----------
__global__ void __launch_bounds__(512)
k_tail(const float* __restrict__ Wih, const float* __restrict__ bih,
       const float* __restrict__ bhh, const float* __restrict__ Whh,
       const float* __restrict__ Wp1, const float* __restrict__ bp1,
       const float* __restrict__ Wp2, const float* __restrict__ bp2,
       const float* __restrict__ Wp3, const float* __restrict__ bp3,
       float* __restrict__ out) {
    __shared__ float2 sp[16][32];
    __shared__ __align__(16) float spool[64];
    int t = threadIdx.x;
    int bt = blockIdx.x;

    // ---- pool phase ----
    {
        int d2 = t & 31;
        int part = t >> 5;   // 16 partials
        const __half2* bp = (const __half2*)(g_h1 + bt * NDP) + d2;
        float2 a = make_float2(0.f, 0.f);
        for (int n0 = part; n0 < NN; n0 += 16) {
            float2 v = __half22float2(bp[n0 * 32]);
            a.x += v.x;
            a.y += v.y;
        }
        sp[part][d2] = a;
        __syncthreads();
        if (part == 0) {
            float2 tt = sp[0][d2];
            #pragma unroll
            for (int i = 1; i < 16; i++) {
                float2 v = sp[i][d2];
                tt.x += v.x;
                tt.y += v.y;
            }
            spool[2 * d2]     = tt.x * (1.0f / NN);
            spool[2 * d2 + 1] = tt.y * (1.0f / NN);
        }
    }
    __syncthreads();

    // ---- gx phase: gx[bt][g] = pooled . Wih[g] + bih[g] + bhh[g] --------
    if (t < 256) {
        int g = t;
        float acc = __ldg(&bih[g]) + __ldg(&bhh[g]);
        const float4* wr = (const float4*)(Wih + (g << 6));
        #pragma unroll
        for (int k4 = 0; k4 < 16; k4++) {
            float4 w = __ldg(wr + k4);
            float4 xv = *(const float4*)&spool[k4 << 2];
            acc += xv.x * w.x + xv.y * w.y + xv.z * w.z + xv.w * w.w;
        }
        g_gx[bt * 256 + g] = acc;
    }
    __syncthreads();

    // ---- barrier: non-zero blocks arrive and exit; block 0 waits --------
    if (blockIdx.x != 0) {
        if (t == 0) {
            __threadfence();
            atomicAdd(&g_cnt, 1);
        }
        return;
    }
    if (t == 0) {
        while (*(volatile unsigned*)&g_cnt != BTB - 1) { __nanosleep(32); }
        atomicExch(&g_cnt, 0);   // reset for next launch
        __threadfence();
    }
    __syncthreads();

    // ---- LSTM recurrence (512 threads: gate g = t>>1, k-half q = t&1) ---
    __shared__ __align__(16) float sh[NB][DD];
    __shared__ float sg[NB][4 * DD];
    __shared__ float sz1[NB][2 * DD], sz2[NB][DD];
    int g = t >> 1, q = t & 1;

    float wh[32];
    {
        const float4* wr = (const float4*)(Whh + (g << 6) + (q << 5));
        #pragma unroll
        for (int i = 0; i < 8; i++) {
            float4 w = __ldg(wr + i);
            wh[4 * i] = w.x; wh[4 * i + 1] = w.y;
            wh[4 * i + 2] = w.z; wh[4 * i + 3] = w.w;
        }
    }
    int bA = q << 1, bB = bA + 1;
    float gxA[NT], gxB[NT];
    #pragma unroll
    for (int tt = 0; tt < NT; tt++) {
        gxA[tt] = __ldg(&g_gx[(bA * NT + tt) * 256 + g]);
        gxB[tt] = __ldg(&g_gx[(bB * NT + tt) * 256 + g]);
    }

    float creg = 0.0f;
    if (t < 256) sh[t >> 6][t & 63] = 0.0f;
    __syncthreads();

    #pragma unroll 1
    for (int step = 0; step < NT; step++) {
        float s0 = 0.f, s1 = 0.f, s2 = 0.f, s3 = 0.f;
        #pragma unroll
        for (int i = 0; i < 8; i++) {
            int off = (q << 5) + (i << 2);
            float4 h0 = *(const float4*)&sh[0][off];
            float4 h1 = *(const float4*)&sh[1][off];
            float4 h2 = *(const float4*)&sh[2][off];
            float4 h3 = *(const float4*)&sh[3][off];
            float w0 = wh[4 * i], w1 = wh[4 * i + 1], w2 = wh[4 * i + 2], w3 = wh[4 * i + 3];
            s0 += h0.x * w0 + h0.y * w1 + h0.z * w2 + h0.w * w3;
            s1 += h1.x * w0 + h1.y * w1 + h1.z * w2 + h1.w * w3;
            s2 += h2.x * w0 + h2.y * w1 + h2.z * w2 + h2.w * w3;
            s3 += h3.x * w0 + h3.y * w1 + h3.z * w2 + h3.w * w3;
        }
        s0 += __shfl_xor_sync(0xffffffffu, s0, 1);
        s1 += __shfl_xor_sync(0xffffffffu, s1, 1);
        s2 += __shfl_xor_sync(0xffffffffu, s2, 1);
        s3 += __shfl_xor_sync(0xffffffffu, s3, 1);
        float selA = (q == 0) ? s0 : s2;
        float selB = (q == 0) ? s1 : s3;
        sg[bA][g] = gxA[step] + selA;
        sg[bB][g] = gxB[step] + selB;
        __syncthreads();
        if (t < 256) {
            int b = t >> 6, d = t & 63;
            float ig = fsig(sg[b][d]);
            float fg = fsig(sg[b][64 + d]);
            float gv = tanhf(sg[b][128 + d]);
            float og = fsig(sg[b][192 + d]);
            creg = fg * creg + ig * gv;
            sh[b][d] = og * tanhf(creg);
        }
        __syncthreads();
    }

    // head: 64 -> 128 (silu) -> 64 (silu) -> 8
    {
        int b = t >> 7, j = t & 127;
        float acc = __ldg(&bp1[j]);
        #pragma unroll
        for (int k = 0; k < 64; k++) acc += sh[b][k] * __ldg(&Wp1[k * 128 + j]);
        sz1[b][j] = fsilu(acc);
    }
    __syncthreads();
    if (t < 256) {
        int b = t >> 6, j2 = t & 63;
        float acc = __ldg(&bp2[j2]);
        #pragma unroll
        for (int j = 0; j < 128; j++) acc += sz1[b][j] * __ldg(&Wp2[j * 64 + j2]);
        sz2[b][j2] = fsilu(acc);
    }
    __syncthreads();
    if (t < 32) {
        int b = t >> 3, o = t & 7;
        float acc = __ldg(&bp3[o]);
        #pragma unroll
        for (int j2 = 0; j2 < 64; j2++) acc += sz2[b][j2] * __ldg(&Wp3[j2 * 8 + o]);
        out[b * 8 + o] = acc;
    }
}

// ---------------- launch --------------------------------------------------
extern "C" void kernel_launch(void* const* d_in, const int* in_sizes, int n_in,
                              void* d_out, int out_size) {
    const float* x   = (const float*)d_in[0];
    const void*  ei  = d_in[1];
    const float* W1  = (const float*)d_in[2];
    const float* b1  = (const float*)d_in[3];
    const float* W2  = (const float*)d_in[4];
    const float* b2  = (const float*)d_in[5];
    const float* W3  = (const float*)d_in[6];
    const float* b3  = (const float*)d_in[7];
    const float* Wih = (const float*)d_in[8];
    const float* Whh = (const float*)d_in[9];
    const float* bih = (const float*)d_in[10];
    const float* bhh = (const float*)d_in[11];
    const float* Wp1 = (const float*)d_in[12];
    const float* bp1 = (const float*)d_in[13];
    const float* Wp2 = (const float*)d_in[14];
    const float* bp2 = (const float*)d_in[15];
    const float* Wp3 = (const float*)d_in[16];
    const float* bp3 = (const float*)d_in[17];
    float* out = (float*)d_out;

    k_prep<<<PBLK, 256>>>(x, ei, W1, W2, W3, b1, b2, b3);
    k_gcn3<<<GBLK, 256>>>();
    k_tail<<<BTB, 512>>>(Wih, bih, bhh, Whh,
                         Wp1, bp1, Wp2, bp2, Wp3, bp3, out);
}